// round 10
// baseline (speedup 1.0000x reference)
#include <cuda_runtime.h>

// ---------------- problem constants ----------------
#define T_TOTAL 35968706LL          // sum of all 52 weight-tensor sizes
#define NV (T_TOTAL / 2)            // float2 count per row (T even)
#define ENC_BLOCKS 592              // 4 blocks/SM on 148 SMs; all co-resident
#define ENC_THREADS 256
#define ENC_NT (ENC_BLOCKS * ENC_THREADS)   // 151,552 threads

// ---------------- device scratch (no allocs allowed) ----------------
__device__ float g_c1[4 * 4  * 112 * 112];
__device__ float g_c2[4 * 8  * 56  * 56];
__device__ float g_c3[4 * 16 * 28  * 28];
__device__ float g_c4[4 * 32 * 14  * 14];
__device__ float g_c5[4 * 64 * 7   * 7];
__device__ float g_q[64];                 // q[b][j]
__device__ unsigned g_cnt[8];             // barrier arrive counters (self-reset)
__device__ unsigned g_epoch[8];           // barrier release epochs (monotonic)

// ---------------- self-resetting grid barrier with backoff spin ----------
__device__ __forceinline__ void grid_bar(int id) {
    __syncthreads();
    if (threadIdx.x == 0) {
        __threadfence();
        unsigned my_epoch = *((volatile unsigned*)&g_epoch[id]);
        unsigned prev = atomicAdd(&g_cnt[id], 1u);
        if (prev == (unsigned)(ENC_BLOCKS - 1)) {
            atomicSub(&g_cnt[id], (unsigned)ENC_BLOCKS);   // reset for next launch
            atomicAdd(&g_epoch[id], 1u);                    // release
        } else {
            while (*((volatile unsigned*)&g_epoch[id]) == my_epoch)
                __nanosleep(256);                           // backoff: ~1 poll/256ns
        }
        __threadfence();
    }
    __syncthreads();
}

// ---- final sync: arrive-only; returns true (whole block) for LAST arriver ----
__device__ __forceinline__ bool arrive_last(int id) {
    __shared__ int s_last;
    __syncthreads();
    if (threadIdx.x == 0) {
        __threadfence();
        unsigned prev = atomicAdd(&g_cnt[id], 1u);
        if (prev == (unsigned)(ENC_BLOCKS - 1)) {
            atomicSub(&g_cnt[id], (unsigned)ENC_BLOCKS);   // self-reset
            __threadfence();                                // all conv5 writes visible
            s_last = 1;
        } else {
            s_last = 0;
        }
    }
    __syncthreads();
    return s_last != 0;
}

// ---------------- conv stage (k=4,s=2,p=1) with L-lane cooperation ----------
template<int CIN, int L, bool LRELU>
__device__ __forceinline__ void conv_stage(
    const float* __restrict__ x, const float* __restrict__ w,
    const float* __restrict__ bias, float* __restrict__ y,
    int Hin, int Win, int Cout, int Hout, int Wout, int gt)
{
    constexpr int CPL = CIN / L;          // channels per lane (all uses divide)
    const int sub   = gt % L;
    const int slot0 = gt / L;
    const int SLOTS = ENC_NT / L;
    const int total = 4 * Cout * Hout * Wout;

    for (int base = 0; base < total; base += SLOTS) {
        int slot = slot0 + base;
        bool active = (slot < total);
        int s = active ? slot : 0;

        int ow = s % Wout; int t = s / Wout;
        int oh = t % Hout; t /= Hout;
        int co = t % Cout; int n = t / Cout;

        int ih0 = oh * 2 - 1, iw0 = ow * 2 - 1;
        const float* xn = x + ((long long)n * CIN + sub * CPL) * Hin * Win;
        const float* wc = w + ((long long)co * CIN + sub * CPL) * 16;

        float acc = 0.f;
        if (active) {
            #pragma unroll
            for (int ci = 0; ci < CPL; ci++) {
                const float* xc = xn + ci * Hin * Win;
                const float* wk = wc + ci * 16;
                #pragma unroll
                for (int kh = 0; kh < 4; kh++) {
                    int ih = ih0 + kh;
                    if ((unsigned)ih >= (unsigned)Hin) continue;
                    const float* xr = xc + ih * Win;
                    #pragma unroll
                    for (int kw = 0; kw < 4; kw++) {
                        int iw = iw0 + kw;
                        if ((unsigned)iw < (unsigned)Win)
                            acc = fmaf(xr[iw], wk[kh * 4 + kw], acc);
                    }
                }
            }
        }
        #pragma unroll
        for (int off = L / 2; off > 0; off >>= 1)
            acc += __shfl_xor_sync(0xffffffffu, acc, off);

        if (active && sub == 0) {
            acc += bias[co];
            if (LRELU) acc = (acc >= 0.f) ? acc : 0.01f * acc;
            y[slot] = acc;
        }
    }
}

// ---------------- fused encoder: 5 convs + head, ONE kernel ----------------
__global__ void __launch_bounds__(ENC_THREADS, 4)
enc_k(const float* __restrict__ rgb,
      const float* __restrict__ cw1, const float* __restrict__ cb1,
      const float* __restrict__ cw2, const float* __restrict__ cb2,
      const float* __restrict__ cw3, const float* __restrict__ cb3,
      const float* __restrict__ cw4, const float* __restrict__ cb4,
      const float* __restrict__ cw5, const float* __restrict__ cb5,
      const float* __restrict__ fc1w, const float* __restrict__ fc1b,
      const float* __restrict__ fc2w, const float* __restrict__ fc2b,
      const float* __restrict__ emb,
      float* __restrict__ loss_out)
{
    int gt = blockIdx.x * ENC_THREADS + threadIdx.x;

    conv_stage<3, 1, true >(rgb,  cw1, cb1, g_c1, 224, 224, 4,  112, 112, gt);
    grid_bar(0);
    conv_stage<4, 1, true >(g_c1, cw2, cb2, g_c2, 112, 112, 8,  56,  56,  gt);
    grid_bar(1);
    conv_stage<8, 2, true >(g_c2, cw3, cb3, g_c3, 56,  56,  16, 28,  28,  gt);
    grid_bar(2);
    conv_stage<16,4, true >(g_c3, cw4, cb4, g_c4, 28,  28,  32, 14,  14,  gt);
    grid_bar(3);
    conv_stage<32,8, false>(g_c4, cw5, cb5, g_c5, 14,  14,  64, 7,   7,   gt);

    // ---- final sync: 591 blocks arrive & exit; the LAST arriver does the head ----
    if (!arrive_last(4)) return;

    __shared__ float sx[4][64];
    __shared__ float sh[4][16];
    __shared__ float se[4][16];
    __shared__ int   sidx[4];
    __shared__ float sred[64];
    int tid = threadIdx.x;

    {   // adaptive avg pool 7x7
        int b = tid >> 6, c = tid & 63;
        const float* p = g_c5 + (b * 64 + c) * 49;
        float s = 0.f;
        #pragma unroll
        for (int i = 0; i < 49; i++) s += p[i];
        sx[b][c] = s * (1.f / 49.f);
    }
    __syncthreads();

    if (tid < 64) {   // fc1 (64->16) + lrelu
        int b = tid >> 4, j = tid & 15;
        float s = fc1b[j];
        #pragma unroll
        for (int k = 0; k < 64; k++) s += sx[b][k] * fc1w[j * 64 + k];
        sh[b][j] = (s >= 0.f) ? s : 0.01f * s;
    }
    __syncthreads();

    if (tid < 64) {   // fc2 (16->16)
        int b = tid >> 4, j = tid & 15;
        float s = fc2b[j];
        #pragma unroll
        for (int k = 0; k < 16; k++) s += sh[b][k] * fc2w[j * 16 + k];
        se[b][j] = s;
    }
    __syncthreads();

    if (tid < 4) {    // VQ argmin (first-min like jnp.argmin)
        int b = tid;
        float ee = 0.f;
        #pragma unroll
        for (int j = 0; j < 16; j++) ee += se[b][j] * se[b][j];
        float best = __int_as_float(0x7f800000);
        int bi = 0;
        for (int c = 0; c < 4; c++) {
            float s2 = 0.f, dot = 0.f;
            #pragma unroll
            for (int j = 0; j < 16; j++) {
                float w = emb[c * 16 + j];
                s2  += w * w;
                dot += w * se[b][j];
            }
            float d = ee + s2 - 2.f * dot;
            if (d < best) { best = d; bi = c; }
        }
        sidx[b] = bi;
    }
    __syncthreads();

    if (tid < 64) {   // q to global + loss = 1.25 * mean((q - e)^2)
        int b = tid >> 4, j = tid & 15;
        float qv = emb[sidx[b] * 16 + j];
        g_q[tid] = qv;
        float diff = qv - se[b][j];
        sred[tid] = diff * diff;
    }
    __syncthreads();
    if (tid == 0) {
        float s = 0.f;
        for (int i = 0; i < 64; i++) s += sred[i];
        *loss_out = 1.25f * s * (1.f / 64.f);
    }
}

// ---------------- the big streaming GEMM: out = q @ W_all (R4-verified) ----
__global__ void __launch_bounds__(256)
gemm_k(const float* __restrict__ W, float* __restrict__ out)
{
    __shared__ float sq[64];
    if (threadIdx.x < 64) sq[threadIdx.x] = g_q[threadIdx.x];
    __syncthreads();

    long long i = (long long)blockIdx.x * blockDim.x + threadIdx.x;
    if (i >= NV) return;

    const float2* __restrict__ W2 = (const float2*)W;
    float2 a0 = {0.f, 0.f}, a1 = {0.f, 0.f}, a2 = {0.f, 0.f}, a3 = {0.f, 0.f};

    #pragma unroll
    for (int k = 0; k < 16; k++) {
        float2 w = __ldcs(&W2[(long long)k * NV + i]);
        float q0 = sq[k], q1 = sq[16 + k], q2 = sq[32 + k], q3 = sq[48 + k];
        a0.x = fmaf(q0, w.x, a0.x); a0.y = fmaf(q0, w.y, a0.y);
        a1.x = fmaf(q1, w.x, a1.x); a1.y = fmaf(q1, w.y, a1.y);
        a2.x = fmaf(q2, w.x, a2.x); a2.y = fmaf(q2, w.y, a2.y);
        a3.x = fmaf(q3, w.x, a3.x); a3.y = fmaf(q3, w.y, a3.y);
    }

    float2* __restrict__ O2 = (float2*)out;
    __stcs(&O2[i],          a0);
    __stcs(&O2[NV + i],     a1);
    __stcs(&O2[2 * NV + i], a2);
    __stcs(&O2[3 * NV + i], a3);
}

// ---------------- launch ----------------
extern "C" void kernel_launch(void* const* d_in, const int* in_sizes, int n_in,
                              void* d_out, int out_size)
{
    const float* rgb   = (const float*)d_in[0];
    const float* cw1   = (const float*)d_in[1];
    const float* cb1   = (const float*)d_in[2];
    const float* cw2   = (const float*)d_in[3];
    const float* cb2   = (const float*)d_in[4];
    const float* cw3   = (const float*)d_in[5];
    const float* cb3   = (const float*)d_in[6];
    const float* cw4   = (const float*)d_in[7];
    const float* cb4   = (const float*)d_in[8];
    const float* cw5   = (const float*)d_in[9];
    const float* cb5   = (const float*)d_in[10];
    const float* fc1w  = (const float*)d_in[11];
    const float* fc1b  = (const float*)d_in[12];
    const float* fc2w  = (const float*)d_in[13];
    const float* fc2b  = (const float*)d_in[14];
    const float* emb   = (const float*)d_in[15];
    const float* Wall  = (const float*)d_in[16];
    float* out = (float*)d_out;

    // one fused encoder kernel (serial, cooperative, self-resetting barriers)
    enc_k<<<ENC_BLOCKS, ENC_THREADS>>>(rgb, cw1, cb1, cw2, cb2, cw3, cb3,
                                       cw4, cb4, cw5, cb5, fc1w, fc1b,
                                       fc2w, fc2b, emb,
                                       out + (long long)out_size - 1);

    // big streaming GEMM (unchanged from the 454.8us best)
    const int TB = 256;
    long long nblocks = (NV + TB - 1) / TB;
    gemm_k<<<(unsigned)nblocks, TB>>>(Wall, out);
}

// round 12
// speedup vs baseline: 1.0233x; 1.0233x over previous
#include <cuda_runtime.h>

// ---------------- problem constants ----------------
#define T_TOTAL 35968706LL          // sum of all 52 weight-tensor sizes
#define NV (T_TOTAL / 2)            // float2 count per row (T even)
#define C5_BLOCKS 784

// ---------------- device scratch (no allocs allowed) ----------------
__device__ float g_c1[4 * 4  * 112 * 112];
__device__ float g_c2[4 * 8  * 56  * 56];
__device__ float g_c3[4 * 16 * 28  * 28];
__device__ float g_c4[4 * 32 * 14  * 14];
__device__ float g_c5[4 * 64 * 7   * 7];
__device__ float g_q[64];                 // q[b][j]
__device__ unsigned g_cnt[4];             // arrive counters (self-reset each use)

// ---------------- split-K conv: k=4, s=2, p=1 (R4 structure, MLP-optimized) --
// Block = 256 threads = OPT outputs x G channel-groups; shared-mem reduce.
// Weights preloaded to registers (float4, 64B-aligned); interior outputs take
// an unguarded 16-load batch per channel; 4 accumulators break the FMA chain.
template<int CIN, int G, bool LRELU>
__device__ __forceinline__ void conv_body(
    const float* __restrict__ x, const float* __restrict__ w,
    const float* __restrict__ bias, float* __restrict__ y,
    int Hin, int Win, int Cout, int Hout, int Wout)
{
    constexpr int OPT = 256 / G;      // outputs per block
    constexpr int CPG = CIN / G;      // channels per group
    const int tid = threadIdx.x;
    const int g   = tid / OPT;
    const int ol  = tid % OPT;

    long long oidx = (long long)blockIdx.x * OPT + ol;
    int ow = (int)(oidx % Wout); long long t = oidx / Wout;
    int oh = (int)(t % Hout);    t /= Hout;
    int co = (int)(t % Cout);
    int n  = (int)(t / Cout);

    const int ih0 = oh * 2 - 1, iw0 = ow * 2 - 1;
    const float* xn = x + ((long long)n * CIN + g * CPG) * Hin * Win;
    const float* wc = w + ((long long)co * CIN + g * CPG) * 16;

    // preload weights: CPG x 16 floats, 64B-aligned -> float4 loads
    float wr[CPG][16];
    #pragma unroll
    for (int ci = 0; ci < CPG; ci++) {
        const float4* w4 = (const float4*)(wc + ci * 16);
        #pragma unroll
        for (int v = 0; v < 4; v++) {
            float4 f = w4[v];
            wr[ci][v*4+0] = f.x; wr[ci][v*4+1] = f.y;
            wr[ci][v*4+2] = f.z; wr[ci][v*4+3] = f.w;
        }
    }

    float a0 = 0.f, a1 = 0.f, a2 = 0.f, a3 = 0.f;
    const bool interior = (ih0 >= 0) & (ih0 + 4 <= Hin) & (iw0 >= 0) & (iw0 + 4 <= Win);

    if (interior) {
        #pragma unroll
        for (int ci = 0; ci < CPG; ci++) {
            const float* xc = xn + ci * Hin * Win + ih0 * Win + iw0;
            float xv[16];
            #pragma unroll
            for (int kh = 0; kh < 4; kh++) {
                #pragma unroll
                for (int kw = 0; kw < 4; kw++)
                    xv[kh*4+kw] = xc[kh * Win + kw];     // 16 independent loads
            }
            #pragma unroll
            for (int kw = 0; kw < 4; kw++) {
                a0 = fmaf(xv[0*4+kw], wr[ci][0*4+kw], a0);
                a1 = fmaf(xv[1*4+kw], wr[ci][1*4+kw], a1);
                a2 = fmaf(xv[2*4+kw], wr[ci][2*4+kw], a2);
                a3 = fmaf(xv[3*4+kw], wr[ci][3*4+kw], a3);
            }
        }
    } else {
        #pragma unroll
        for (int ci = 0; ci < CPG; ci++) {
            const float* xc = xn + ci * Hin * Win;
            #pragma unroll
            for (int kh = 0; kh < 4; kh++) {
                int ih = ih0 + kh;
                if ((unsigned)ih >= (unsigned)Hin) continue;
                const float* xr = xc + ih * Win;
                float part = 0.f;
                #pragma unroll
                for (int kw = 0; kw < 4; kw++) {
                    int iw = iw0 + kw;
                    if ((unsigned)iw < (unsigned)Win)
                        part = fmaf(xr[iw], wr[ci][kh*4+kw], part);
                }
                if (kh == 0) a0 += part; else if (kh == 1) a1 += part;
                else if (kh == 2) a2 += part; else a3 += part;
            }
        }
    }
    float acc = (a0 + a1) + (a2 + a3);

    if (G == 1) {
        acc += bias[co];
        if (LRELU) acc = (acc >= 0.f) ? acc : 0.01f * acc;
        y[oidx] = acc;
    } else {
        __shared__ float s[256];
        s[tid] = acc;
        __syncthreads();
        if (g == 0) {
            float sum = acc;
            #pragma unroll
            for (int j = 1; j < G; j++) sum += s[j * OPT + ol];
            sum += bias[co];
            if (LRELU) sum = (sum >= 0.f) ? sum : 0.01f * sum;
            y[oidx] = sum;
        }
    }
}

template<int CIN, int G, bool LRELU>
__global__ void __launch_bounds__(256)
conv_split(const float* __restrict__ x, const float* __restrict__ w,
           const float* __restrict__ bias, float* __restrict__ y,
           int Hin, int Win, int Cout, int Hout, int Wout)
{
    conv_body<CIN, G, LRELU>(x, w, bias, y, Hin, Win, Cout, Hout, Wout);
}

// ---------------- conv5 + head fused (arrive-last; no spinning) -------------
__global__ void __launch_bounds__(256)
conv5_head_k(const float* __restrict__ x, const float* __restrict__ w,
             const float* __restrict__ bias,
             const float* __restrict__ fc1w, const float* __restrict__ fc1b,
             const float* __restrict__ fc2w, const float* __restrict__ fc2b,
             const float* __restrict__ emb,
             float* __restrict__ loss_out)
{
    conv_body<32, 16, false>(x, w, bias, g_c5, 14, 14, 64, 7, 7);

    // arrive-only: 783 blocks exit; the LAST arriver (all its threads) does the head
    __shared__ int s_last;
    __syncthreads();
    if (threadIdx.x == 0) {
        __threadfence();                                 // release my g_c5 writes
        unsigned prev = atomicAdd(&g_cnt[0], 1u);
        if (prev == (unsigned)(C5_BLOCKS - 1)) {
            atomicSub(&g_cnt[0], (unsigned)C5_BLOCKS);   // self-reset for next replay
            __threadfence();                             // acquire all writers
            s_last = 1;
        } else s_last = 0;
    }
    __syncthreads();
    if (!s_last) return;

    __shared__ float sx[4][64];
    __shared__ float sh[4][16];
    __shared__ float se[4][16];
    __shared__ int   sidx[4];
    __shared__ float sred[64];
    int tid = threadIdx.x;

    {   // adaptive avg pool 7x7
        int b = tid >> 6, c = tid & 63;
        const float* p = g_c5 + (b * 64 + c) * 49;
        float s = 0.f;
        #pragma unroll
        for (int i = 0; i < 49; i++) s += p[i];
        sx[b][c] = s * (1.f / 49.f);
    }
    __syncthreads();

    if (tid < 64) {   // fc1 (64->16) + lrelu
        int b = tid >> 4, j = tid & 15;
        float s = fc1b[j];
        #pragma unroll
        for (int k = 0; k < 64; k++) s += sx[b][k] * fc1w[j * 64 + k];
        sh[b][j] = (s >= 0.f) ? s : 0.01f * s;
    }
    __syncthreads();

    if (tid < 64) {   // fc2 (16->16)
        int b = tid >> 4, j = tid & 15;
        float s = fc2b[j];
        #pragma unroll
        for (int k = 0; k < 16; k++) s += sh[b][k] * fc2w[j * 16 + k];
        se[b][j] = s;
    }
    __syncthreads();

    if (tid < 4) {    // VQ argmin (first-min like jnp.argmin)
        int b = tid;
        float ee = 0.f;
        #pragma unroll
        for (int j = 0; j < 16; j++) ee += se[b][j] * se[b][j];
        float best = __int_as_float(0x7f800000);
        int bi = 0;
        for (int c = 0; c < 4; c++) {
            float s2 = 0.f, dot = 0.f;
            #pragma unroll
            for (int j = 0; j < 16; j++) {
                float w2 = emb[c * 16 + j];
                s2  += w2 * w2;
                dot += w2 * se[b][j];
            }
            float d = ee + s2 - 2.f * dot;
            if (d < best) { best = d; bi = c; }
        }
        sidx[b] = bi;
    }
    __syncthreads();

    if (tid < 64) {   // q to global + loss = 1.25 * mean((q - e)^2)
        int b = tid >> 4, j = tid & 15;
        float qv = emb[sidx[b] * 16 + j];
        g_q[tid] = qv;
        float diff = qv - se[b][j];
        sred[tid] = diff * diff;
    }
    __syncthreads();
    if (tid == 0) {
        float s = 0.f;
        for (int i = 0; i < 64; i++) s += sred[i];
        *loss_out = 1.25f * s * (1.f / 64.f);
    }
}

// ---------------- the big streaming GEMM: out = q @ W_all (R4-verified) ----
__global__ void __launch_bounds__(256)
gemm_k(const float* __restrict__ W, float* __restrict__ out)
{
    __shared__ float sq[64];
    if (threadIdx.x < 64) sq[threadIdx.x] = g_q[threadIdx.x];
    __syncthreads();

    long long i = (long long)blockIdx.x * blockDim.x + threadIdx.x;
    if (i >= NV) return;

    const float2* __restrict__ W2 = (const float2*)W;
    float2 a0 = {0.f, 0.f}, a1 = {0.f, 0.f}, a2 = {0.f, 0.f}, a3 = {0.f, 0.f};

    #pragma unroll
    for (int k = 0; k < 16; k++) {
        float2 w = __ldcs(&W2[(long long)k * NV + i]);
        float q0 = sq[k], q1 = sq[16 + k], q2 = sq[32 + k], q3 = sq[48 + k];
        a0.x = fmaf(q0, w.x, a0.x); a0.y = fmaf(q0, w.y, a0.y);
        a1.x = fmaf(q1, w.x, a1.x); a1.y = fmaf(q1, w.y, a1.y);
        a2.x = fmaf(q2, w.x, a2.x); a2.y = fmaf(q2, w.y, a2.y);
        a3.x = fmaf(q3, w.x, a3.x); a3.y = fmaf(q3, w.y, a3.y);
    }

    float2* __restrict__ O2 = (float2*)out;
    __stcs(&O2[i],          a0);
    __stcs(&O2[NV + i],     a1);
    __stcs(&O2[2 * NV + i], a2);
    __stcs(&O2[3 * NV + i], a3);
}

// ---------------- launch ----------------
extern "C" void kernel_launch(void* const* d_in, const int* in_sizes, int n_in,
                              void* d_out, int out_size)
{
    const float* rgb   = (const float*)d_in[0];
    const float* cw1   = (const float*)d_in[1];
    const float* cb1   = (const float*)d_in[2];
    const float* cw2   = (const float*)d_in[3];
    const float* cb2   = (const float*)d_in[4];
    const float* cw3   = (const float*)d_in[5];
    const float* cb3   = (const float*)d_in[6];
    const float* cw4   = (const float*)d_in[7];
    const float* cb4   = (const float*)d_in[8];
    const float* cw5   = (const float*)d_in[9];
    const float* cb5   = (const float*)d_in[10];
    const float* fc1w  = (const float*)d_in[11];
    const float* fc1b  = (const float*)d_in[12];
    const float* fc2w  = (const float*)d_in[13];
    const float* fc2b  = (const float*)d_in[14];
    const float* emb   = (const float*)d_in[15];
    const float* Wall  = (const float*)d_in[16];
    float* out = (float*)d_out;

    float *c1, *c2, *c3, *c4;
    cudaGetSymbolAddress((void**)&c1, g_c1);
    cudaGetSymbolAddress((void**)&c2, g_c2);
    cudaGetSymbolAddress((void**)&c3, g_c3);
    cudaGetSymbolAddress((void**)&c4, g_c4);

    // outputs/layer:          200704    100352     50176     25088     12544
    // OPT (=256/G):              256       128        64        32        16
    // blocks:                    784       784       784       784       784
    conv_split<3, 1,  true ><<<784, 256>>>(rgb, cw1, cb1, c1, 224, 224, 4, 112, 112);
    conv_split<4, 2,  true ><<<784, 256>>>(c1,  cw2, cb2, c2, 112, 112, 8,  56,  56);
    conv_split<8, 4,  true ><<<784, 256>>>(c2,  cw3, cb3, c3,  56,  56, 16, 28,  28);
    conv_split<16,8,  true ><<<784, 256>>>(c3,  cw4, cb4, c4,  28,  28, 32, 14,  14);

    // conv5 + head fused (arrive-last; loss at the final output element)
    conv5_head_k<<<C5_BLOCKS, 256>>>(c4, cw5, cb5, fc1w, fc1b, fc2w, fc2b, emb,
                                     out + (long long)out_size - 1);

    // big streaming GEMM (unchanged from the 454.8us best)
    const int TB = 256;
    long long nblocks = (NV + TB - 1) / TB;
    gemm_k<<<(unsigned)nblocks, TB>>>(Wall, out);
}

// round 13
// speedup vs baseline: 1.0327x; 1.0091x over previous
#include <cuda_runtime.h>

// ---------------- problem constants ----------------
#define T_TOTAL 35968706LL          // sum of all 52 weight-tensor sizes
#define NV (T_TOTAL / 2)            // float2 count per row (T even)
#define ENC_BLOCKS 784              // every stage uses exactly 784 blocks (R4 layout)
#define ENC_THREADS 256

// ---------------- device scratch (no allocs allowed) ----------------
__device__ float g_c1[4 * 4  * 112 * 112];
__device__ float g_c2[4 * 8  * 56  * 56];
__device__ float g_c3[4 * 16 * 28  * 28];
__device__ float g_c4[4 * 32 * 14  * 14];
__device__ float g_c5[4 * 64 * 7   * 7];
__device__ float g_q[64];                 // q[b][j]
__device__ unsigned g_cnt[8];             // barrier counters (self-reset)
__device__ unsigned g_epoch[8];           // barrier epochs (monotonic across replays)

// ---------------- self-resetting grid barrier with backoff spin ------------
// All ENC_BLOCKS co-resident: 784 blocks <= 148 SMs * 8 blocks/SM
// (256 thr, ~31 regs). Epoch is monotonic, counter self-resets -> no init
// kernel, launch-invariant state, graph-replay safe.
__device__ __forceinline__ void grid_bar(int id) {
    __syncthreads();
    if (threadIdx.x == 0) {
        __threadfence();
        unsigned my_epoch = *((volatile unsigned*)&g_epoch[id]);
        unsigned prev = atomicAdd(&g_cnt[id], 1u);
        if (prev == (unsigned)(ENC_BLOCKS - 1)) {
            atomicSub(&g_cnt[id], (unsigned)ENC_BLOCKS);
            atomicAdd(&g_epoch[id], 1u);                 // release
        } else {
            while (*((volatile unsigned*)&g_epoch[id]) == my_epoch)
                __nanosleep(128);
        }
        __threadfence();
    }
    __syncthreads();
}

// ---------------- R4-verified conv stage body (k=4, s=2, p=1) --------------
// Block = 256 threads = OPT outputs x G channel-groups, shared-mem reduce.
// Identical math/structure to the 454.8us-best conv_split (31 regs).
template<int CIN, int G, bool LRELU>
__device__ __forceinline__ void conv_body(
    const float* __restrict__ x, const float* __restrict__ w,
    const float* __restrict__ bias, float* __restrict__ y,
    int Hin, int Win, int Cout, int Hout, int Wout)
{
    constexpr int OPT = 256 / G;
    constexpr int CPG = CIN / G;
    const int tid = threadIdx.x;
    const int g   = tid / OPT;
    const int ol  = tid % OPT;

    long long oidx = (long long)blockIdx.x * OPT + ol;
    int ow = (int)(oidx % Wout); long long t = oidx / Wout;
    int oh = (int)(t % Hout);    t /= Hout;
    int co = (int)(t % Cout);
    int n  = (int)(t / Cout);

    const int ih0 = oh * 2 - 1, iw0 = ow * 2 - 1;
    const float* xn = x + ((long long)n * CIN + g * CPG) * Hin * Win;
    const float* wc = w + ((long long)co * CIN + g * CPG) * 16;

    float acc = 0.f;
    #pragma unroll
    for (int ci = 0; ci < CPG; ci++) {
        const float* xc = xn + ci * Hin * Win;
        const float* wk = wc + ci * 16;
        #pragma unroll
        for (int kh = 0; kh < 4; kh++) {
            int ih = ih0 + kh;
            if ((unsigned)ih >= (unsigned)Hin) continue;
            const float* xr = xc + ih * Win;
            #pragma unroll
            for (int kw = 0; kw < 4; kw++) {
                int iw = iw0 + kw;
                if ((unsigned)iw < (unsigned)Win)
                    acc = fmaf(xr[iw], wk[kh * 4 + kw], acc);
            }
        }
    }

    if (G == 1) {
        acc += bias[co];
        if (LRELU) acc = (acc >= 0.f) ? acc : 0.01f * acc;
        y[oidx] = acc;
    } else {
        __shared__ float s[256];
        s[tid] = acc;
        __syncthreads();
        if (g == 0) {
            float sum = acc;
            #pragma unroll
            for (int j = 1; j < G; j++) sum += s[j * OPT + ol];
            sum += bias[co];
            if (LRELU) sum = (sum >= 0.f) ? sum : 0.01f * sum;
            y[oidx] = sum;
        }
        __syncthreads();   // s reused by next stage
    }
}

// ---------------- fused encoder: 5 R4 stages + head, ONE kernel ------------
__global__ void __launch_bounds__(ENC_THREADS)
enc_k(const float* __restrict__ rgb,
      const float* __restrict__ cw1, const float* __restrict__ cb1,
      const float* __restrict__ cw2, const float* __restrict__ cb2,
      const float* __restrict__ cw3, const float* __restrict__ cb3,
      const float* __restrict__ cw4, const float* __restrict__ cb4,
      const float* __restrict__ cw5, const float* __restrict__ cb5,
      const float* __restrict__ fc1w, const float* __restrict__ fc1b,
      const float* __restrict__ fc2w, const float* __restrict__ fc2b,
      const float* __restrict__ emb,
      float* __restrict__ loss_out)
{
    // identical per-block assignments to the R4 launch chain:
    conv_body<3, 1,  true >(rgb,  cw1, cb1, g_c1, 224, 224, 4, 112, 112);
    grid_bar(0);
    conv_body<4, 2,  true >(g_c1, cw2, cb2, g_c2, 112, 112, 8,  56,  56);
    grid_bar(1);
    conv_body<8, 4,  true >(g_c2, cw3, cb3, g_c3,  56,  56, 16, 28,  28);
    grid_bar(2);
    conv_body<16,8,  true >(g_c3, cw4, cb4, g_c4,  28,  28, 32, 14,  14);
    grid_bar(3);
    conv_body<32,16, false>(g_c4, cw5, cb5, g_c5,  14,  14, 64,  7,   7);

    // ---- arrive-last: 783 blocks exit immediately; last arriver runs the head ----
    __shared__ int s_last;
    __syncthreads();
    if (threadIdx.x == 0) {
        __threadfence();                                  // release my g_c5 writes
        unsigned prev = atomicAdd(&g_cnt[4], 1u);
        if (prev == (unsigned)(ENC_BLOCKS - 1)) {
            atomicSub(&g_cnt[4], (unsigned)ENC_BLOCKS);   // self-reset for replay
            __threadfence();                              // acquire all writers
            s_last = 1;
        } else s_last = 0;
    }
    __syncthreads();
    if (!s_last) return;

    __shared__ float sx[4][64];
    __shared__ float sh[4][16];
    __shared__ float se[4][16];
    __shared__ int   sidx[4];
    __shared__ float sred[64];
    int tid = threadIdx.x;

    {   // adaptive avg pool 7x7
        int b = tid >> 6, c = tid & 63;
        const float* p = g_c5 + (b * 64 + c) * 49;
        float s = 0.f;
        #pragma unroll
        for (int i = 0; i < 49; i++) s += p[i];
        sx[b][c] = s * (1.f / 49.f);
    }
    __syncthreads();

    if (tid < 64) {   // fc1 (64->16) + lrelu
        int b = tid >> 4, j = tid & 15;
        float s = fc1b[j];
        #pragma unroll
        for (int k = 0; k < 64; k++) s += sx[b][k] * fc1w[j * 64 + k];
        sh[b][j] = (s >= 0.f) ? s : 0.01f * s;
    }
    __syncthreads();

    if (tid < 64) {   // fc2 (16->16)
        int b = tid >> 4, j = tid & 15;
        float s = fc2b[j];
        #pragma unroll
        for (int k = 0; k < 16; k++) s += sh[b][k] * fc2w[j * 16 + k];
        se[b][j] = s;
    }
    __syncthreads();

    if (tid < 4) {    // VQ argmin (first-min like jnp.argmin)
        int b = tid;
        float ee = 0.f;
        #pragma unroll
        for (int j = 0; j < 16; j++) ee += se[b][j] * se[b][j];
        float best = __int_as_float(0x7f800000);
        int bi = 0;
        for (int c = 0; c < 4; c++) {
            float s2 = 0.f, dot = 0.f;
            #pragma unroll
            for (int j = 0; j < 16; j++) {
                float w = emb[c * 16 + j];
                s2  += w * w;
                dot += w * se[b][j];
            }
            float d = ee + s2 - 2.f * dot;
            if (d < best) { best = d; bi = c; }
        }
        sidx[b] = bi;
    }
    __syncthreads();

    if (tid < 64) {   // q to global + loss = 1.25 * mean((q - e)^2)
        int b = tid >> 4, j = tid & 15;
        float qv = emb[sidx[b] * 16 + j];
        g_q[tid] = qv;
        float diff = qv - se[b][j];
        sred[tid] = diff * diff;
    }
    __syncthreads();
    if (tid == 0) {
        float s = 0.f;
        for (int i = 0; i < 64; i++) s += sred[i];
        *loss_out = 1.25f * s * (1.f / 64.f);
    }
}

// ---------------- the big streaming GEMM: out = q @ W_all (R4-verified) ----
__global__ void __launch_bounds__(256)
gemm_k(const float* __restrict__ W, float* __restrict__ out)
{
    __shared__ float sq[64];
    if (threadIdx.x < 64) sq[threadIdx.x] = g_q[threadIdx.x];
    __syncthreads();

    long long i = (long long)blockIdx.x * blockDim.x + threadIdx.x;
    if (i >= NV) return;

    const float2* __restrict__ W2 = (const float2*)W;
    float2 a0 = {0.f, 0.f}, a1 = {0.f, 0.f}, a2 = {0.f, 0.f}, a3 = {0.f, 0.f};

    #pragma unroll
    for (int k = 0; k < 16; k++) {
        float2 w = __ldcs(&W2[(long long)k * NV + i]);
        float q0 = sq[k], q1 = sq[16 + k], q2 = sq[32 + k], q3 = sq[48 + k];
        a0.x = fmaf(q0, w.x, a0.x); a0.y = fmaf(q0, w.y, a0.y);
        a1.x = fmaf(q1, w.x, a1.x); a1.y = fmaf(q1, w.y, a1.y);
        a2.x = fmaf(q2, w.x, a2.x); a2.y = fmaf(q2, w.y, a2.y);
        a3.x = fmaf(q3, w.x, a3.x); a3.y = fmaf(q3, w.y, a3.y);
    }

    float2* __restrict__ O2 = (float2*)out;
    __stcs(&O2[i],          a0);
    __stcs(&O2[NV + i],     a1);
    __stcs(&O2[2 * NV + i], a2);
    __stcs(&O2[3 * NV + i], a3);
}

// ---------------- launch ----------------
extern "C" void kernel_launch(void* const* d_in, const int* in_sizes, int n_in,
                              void* d_out, int out_size)
{
    const float* rgb   = (const float*)d_in[0];
    const float* cw1   = (const float*)d_in[1];
    const float* cb1   = (const float*)d_in[2];
    const float* cw2   = (const float*)d_in[3];
    const float* cb2   = (const float*)d_in[4];
    const float* cw3   = (const float*)d_in[5];
    const float* cb3   = (const float*)d_in[6];
    const float* cw4   = (const float*)d_in[7];
    const float* cb4   = (const float*)d_in[8];
    const float* cw5   = (const float*)d_in[9];
    const float* cb5   = (const float*)d_in[10];
    const float* fc1w  = (const float*)d_in[11];
    const float* fc1b  = (const float*)d_in[12];
    const float* fc2w  = (const float*)d_in[13];
    const float* fc2b  = (const float*)d_in[14];
    const float* emb   = (const float*)d_in[15];
    const float* Wall  = (const float*)d_in[16];
    float* out = (float*)d_out;

    // one fused encoder kernel: exact R4 per-stage structure + 4 grid barriers
    enc_k<<<ENC_BLOCKS, ENC_THREADS>>>(rgb, cw1, cb1, cw2, cb2, cw3, cb3,
                                       cw4, cb4, cw5, cb5, fc1w, fc1b,
                                       fc2w, fc2b, emb,
                                       out + (long long)out_size - 1);

    // big streaming GEMM (unchanged from the 454.8us best)
    const int TB = 256;
    long long nblocks = (NV + TB - 1) / TB;
    gemm_k<<<(unsigned)nblocks, TB>>>(Wall, out);
}